// round 9
// baseline (speedup 1.0000x reference)
#include <cuda_runtime.h>
#include <cuda_fp16.h>

#define NN 100000
#define EE 3200000
#define EA 3300000     // EE + NN self loops
#define HH 32
#define MM 64
#define CC 10
#define GG 64
#define NB 98          // ceil(NN / 1024) scan blocks
#define NQUAD 25000    // NN / 4
#define E4 800000      // EE / 4
#define T4 825000      // EA / 4 total vector threads

// ---------------- scratch (device globals; no allocation allowed) ----------
__device__ unsigned long long g_packed[NN];   // (count<<32) | fixedpoint(deg)
__device__ int    g_cursor[NN];
__device__ int    g_rowptr[NN + 1];
__device__ float  g_deg[NN];          // dinv after scanA
__device__ int    g_blocksum[NB];
__device__ int    g_blockoff[NB];
__device__ int2   g_cv[EA];           // per-edge: (src, norm bits), CSR by dst
__device__ __half g_A[NN * HH];       // features fp16, [N][32] (gemm output)
__device__ __half g_B[NN * HH];       // agg output
__device__ float  g_pool[GG * HH];
__device__ int    g_cnt[GG];

// ---------------- init -----------------------------------------------------
__global__ void k_zero() {
    int i = blockIdx.x * blockDim.x + threadIdx.x;
    if (i < NN) g_packed[i] = 0ull;
    if (i < GG * HH) g_pool[i] = 0.f;
    if (i < GG) g_cnt[i] = 0;
}

// ---------------- CSR build (x4 vectorized) ---------------------------------
// one 64-bit atomic per edge: count in hi word, deg (fixed point 2^20) in lo
__global__ void k_hist(const int* __restrict__ ei,
                       const float* __restrict__ ew) {
    int t = blockIdx.x * blockDim.x + threadIdx.x;
    if (t >= T4) return;
    if (t < E4) {
        int4   d4 = __ldg(&((const int4*)(ei + EE))[t]);
        float4 w4 = __ldg(&((const float4*)ew)[t]);
        atomicAdd(&g_packed[d4.x], (1ull << 32) |
            (unsigned long long)(unsigned)__float2uint_rn(w4.x * 1048576.f));
        atomicAdd(&g_packed[d4.y], (1ull << 32) |
            (unsigned long long)(unsigned)__float2uint_rn(w4.y * 1048576.f));
        atomicAdd(&g_packed[d4.z], (1ull << 32) |
            (unsigned long long)(unsigned)__float2uint_rn(w4.z * 1048576.f));
        atomicAdd(&g_packed[d4.w], (1ull << 32) |
            (unsigned long long)(unsigned)__float2uint_rn(w4.w * 1048576.f));
    } else {
        int n = (t - E4) * 4;   // self loops, w = 1
        const unsigned long long p = (1ull << 32) | 1048576ull;
        atomicAdd(&g_packed[n + 0], p);
        atomicAdd(&g_packed[n + 1], p);
        atomicAdd(&g_packed[n + 2], p);
        atomicAdd(&g_packed[n + 3], p);
    }
}

// phase A: block-local exclusive scan of counts; fused deg -> dinv
__global__ void __launch_bounds__(1024) k_scanA() {
    __shared__ int wt[32];
    int tid = threadIdx.x;
    int i = blockIdx.x * 1024 + tid;
    unsigned long long p = (i < NN) ? g_packed[i] : 0ull;
    int v = (int)(p >> 32);
    int x = v;
    #pragma unroll
    for (int d = 1; d < 32; d <<= 1) {
        int y = __shfl_up_sync(0xffffffffu, x, d);
        if ((tid & 31) >= d) x += y;
    }
    if ((tid & 31) == 31) wt[tid >> 5] = x;
    __syncthreads();
    if (tid < 32) {
        int t = wt[tid];
        int xx = t;
        #pragma unroll
        for (int d = 1; d < 32; d <<= 1) {
            int y = __shfl_up_sync(0xffffffffu, xx, d);
            if (tid >= d) xx += y;
        }
        wt[tid] = xx - t;   // exclusive warp offsets
    }
    __syncthreads();
    int incl = x + wt[tid >> 5];
    if (i < NN) g_rowptr[i] = incl - v;          // block-local exclusive
    if (tid == 1023) g_blocksum[blockIdx.x] = incl;
    // fused dinv from fixed-point degree
    if (i < NN) {
        float d = (float)(unsigned)(p & 0xffffffffull) * (1.f / 1048576.f);
        g_deg[i] = (d > 0.f) ? rsqrtf(fmaxf(d, 1e-30f)) : 0.f;
    }
}

// phase B: exclusive scan of NB block sums (1 block, 128 threads)
__global__ void k_scanB() {
    __shared__ int wt[4];
    int tid = threadIdx.x;   // 128
    int v = (tid < NB) ? g_blocksum[tid] : 0;
    int x = v;
    #pragma unroll
    for (int d = 1; d < 32; d <<= 1) {
        int y = __shfl_up_sync(0xffffffffu, x, d);
        if ((tid & 31) >= d) x += y;
    }
    if ((tid & 31) == 31) wt[tid >> 5] = x;
    __syncthreads();
    if (tid < 4) {
        int t = wt[tid];
        int xx = t;
        #pragma unroll
        for (int d = 1; d < 4; d <<= 1) {
            int y = __shfl_up_sync(0x0000000fu, xx, d);
            if (tid >= d) xx += y;
        }
        wt[tid] = xx - t;
    }
    __syncthreads();
    int incl = x + wt[tid >> 5];
    if (tid < NB) g_blockoff[tid] = incl - v;
    if (tid == NB - 1) g_rowptr[NN] = incl;
}

// phase C: add block offsets, write final rowptr + cursor
__global__ void __launch_bounds__(1024) k_scanC() {
    int i = blockIdx.x * 1024 + threadIdx.x;
    if (i >= NN) return;
    int out = g_rowptr[i] + g_blockoff[blockIdx.x];
    g_rowptr[i] = out;
    g_cursor[i] = out;
}

// x4 vectorized scatter
__global__ void k_scatter(const int* __restrict__ ei,
                          const float* __restrict__ ew) {
    int t = blockIdx.x * blockDim.x + threadIdx.x;
    if (t >= T4) return;
    if (t < E4) {
        int4   s4 = __ldg(&((const int4*)ei)[t]);
        int4   d4 = __ldg(&((const int4*)(ei + EE))[t]);
        float4 w4 = __ldg(&((const float4*)ew)[t]);
        {
            float nv = g_deg[s4.x] * w4.x * g_deg[d4.x];
            int idx = atomicAdd(&g_cursor[d4.x], 1);
            g_cv[idx] = make_int2(s4.x, __float_as_int(nv));
        }
        {
            float nv = g_deg[s4.y] * w4.y * g_deg[d4.y];
            int idx = atomicAdd(&g_cursor[d4.y], 1);
            g_cv[idx] = make_int2(s4.y, __float_as_int(nv));
        }
        {
            float nv = g_deg[s4.z] * w4.z * g_deg[d4.z];
            int idx = atomicAdd(&g_cursor[d4.z], 1);
            g_cv[idx] = make_int2(s4.z, __float_as_int(nv));
        }
        {
            float nv = g_deg[s4.w] * w4.w * g_deg[d4.w];
            int idx = atomicAdd(&g_cursor[d4.w], 1);
            g_cv[idx] = make_int2(s4.w, __float_as_int(nv));
        }
    } else {
        int n = (t - E4) * 4;   // self loops
        #pragma unroll
        for (int j = 0; j < 4; j++) {
            float dv = g_deg[n + j];
            float nv = dv * dv;
            int idx = atomicAdd(&g_cursor[n + j], 1);
            g_cv[idx] = make_int2(n + j, __float_as_int(nv));
        }
    }
}

// ---------------- GEMM: g_A[N,32] = X[N,128] @ W[128,32] (fp16 out) ---------
__global__ void __launch_bounds__(256) k_gemm128(const float* __restrict__ X,
                                                 const float* __restrict__ W) {
    __shared__ float4 sW[128 * 8];   // W as [k][o/4]
    __shared__ float  sX[256 * 17];  // 16-wide k-chunk, pad 17
    int tid = threadIdx.x;
    for (int i = tid; i < 1024; i += 256) sW[i] = ((const float4*)W)[i];
    float acc[32];
    #pragma unroll
    for (int o = 0; o < 32; o++) acc[o] = 0.f;
    int row = blockIdx.x * 256 + tid;
    for (int kc = 0; kc < 8; kc++) {
        __syncthreads();
        for (int i = tid; i < 256 * 16; i += 256) {
            int r = i >> 4, c = i & 15;
            int rr = blockIdx.x * 256 + r;
            sX[r * 17 + c] = (rr < NN) ? X[rr * 128 + kc * 16 + c] : 0.f;
        }
        __syncthreads();
        #pragma unroll
        for (int kk = 0; kk < 16; kk++) {
            float xv = sX[tid * 17 + kk];
            int k = kc * 16 + kk;
            #pragma unroll
            for (int o4 = 0; o4 < 8; o4++) {
                float4 wv = sW[k * 8 + o4];
                acc[o4 * 4 + 0] += xv * wv.x;
                acc[o4 * 4 + 1] += xv * wv.y;
                acc[o4 * 4 + 2] += xv * wv.z;
                acc[o4 * 4 + 3] += xv * wv.w;
            }
        }
    }
    if (row < NN) {
        __half2* Y2 = (__half2*)g_A;
        #pragma unroll
        for (int j = 0; j < 16; j++)
            Y2[row * 16 + j] = __floats2half2_rn(acc[2 * j], acc[2 * j + 1]);
    }
}

// ---------------- GEMM32: g_A[N,32] = g_B[N,32] @ W[32,32] ------------------
__global__ void __launch_bounds__(256) k_gemm32(const float* __restrict__ W) {
    __shared__ float4 sW[32 * 8];
    __shared__ float  sX[256 * 33];
    int tid = threadIdx.x;
    for (int i = tid; i < 256; i += 256) sW[i] = ((const float4*)W)[i];
    const __half2* in2 = (const __half2*)g_B;
    for (int i = tid; i < 256 * 16; i += 256) {
        int r = i >> 4, c = i & 15;     // c indexes half2 pairs
        int rr = blockIdx.x * 256 + r;
        float2 v = (rr < NN) ? __half22float2(__ldg(&in2[rr * 16 + c]))
                             : make_float2(0.f, 0.f);
        sX[r * 33 + 2 * c]     = v.x;
        sX[r * 33 + 2 * c + 1] = v.y;
    }
    __syncthreads();
    float acc[32];
    #pragma unroll
    for (int o = 0; o < 32; o++) acc[o] = 0.f;
    #pragma unroll
    for (int kk = 0; kk < 32; kk++) {
        float xv = sX[tid * 33 + kk];
        #pragma unroll
        for (int o4 = 0; o4 < 8; o4++) {
            float4 wv = sW[kk * 8 + o4];
            acc[o4 * 4 + 0] += xv * wv.x;
            acc[o4 * 4 + 1] += xv * wv.y;
            acc[o4 * 4 + 2] += xv * wv.z;
            acc[o4 * 4 + 3] += xv * wv.w;
        }
    }
    int row = blockIdx.x * 256 + tid;
    if (row < NN) {
        __half2* Y2 = (__half2*)g_A;
        #pragma unroll
        for (int j = 0; j < 16; j++)
            Y2[row * 16 + j] = __floats2half2_rn(acc[2 * j], acc[2 * j + 1]);
    }
}

// ---------------- edge aggregation: agg(g_A) --------------------------------
// 4 nodes per warp: quarter-warp (8 lanes) per node, lane covers 4 features.
// mode 0: write g_B; mode 1: mean-pool atomics (epilogue only differs).
__global__ void __launch_bounds__(256) k_agg(const float* __restrict__ bias,
                                             int relu, int mode,
                                             const int* __restrict__ batch) {
    int quad = (blockIdx.x * blockDim.x + threadIdx.x) >> 5;
    if (quad >= NQUAD) return;
    int lane = threadIdx.x & 31;
    int q  = lane >> 3;            // node within quad (0..3)
    int ql = lane & 7;             // feature group: features 4*ql .. 4*ql+3
    int node = quad * 4 + q;
    int beg = g_rowptr[node], end = g_rowptr[node + 1];
    int myc = end - beg;
    // max degree across the 4 nodes of this warp
    int m1 = __shfl_xor_sync(0xffffffffu, myc, 8);
    int mx = (myc > m1) ? myc : m1;
    int m2 = __shfl_xor_sync(0xffffffffu, mx, 16);
    int maxit = (mx > m2) ? mx : m2;
    const float2* __restrict__ in2 = (const float2*)g_A;   // 8B = 4 halves
    float4 acc = make_float4(0.f, 0.f, 0.f, 0.f);
    #pragma unroll 4
    for (int it = 0; it < maxit; it++) {
        int e = beg + it;
        if (e < end) {
            int2 cv = __ldg(&g_cv[e]);
            float nv = __int_as_float(cv.y);
            float2 packed = __ldg(&in2[cv.x * 8 + ql]);
            float2 h01 = __half22float2(*(const __half2*)&packed.x);
            float2 h23 = __half22float2(*(const __half2*)&packed.y);
            acc.x += nv * h01.x;
            acc.y += nv * h01.y;
            acc.z += nv * h23.x;
            acc.w += nv * h23.y;
        }
    }
    float4 bv = __ldg(&((const float4*)bias)[ql]);
    acc.x += bv.x; acc.y += bv.y; acc.z += bv.z; acc.w += bv.w;
    if (relu) {
        acc.x = fmaxf(acc.x, 0.f);
        acc.y = fmaxf(acc.y, 0.f);
        acc.z = fmaxf(acc.z, 0.f);
        acc.w = fmaxf(acc.w, 0.f);
    }
    if (mode == 0) {
        __half2 o0 = __floats2half2_rn(acc.x, acc.y);
        __half2 o1 = __floats2half2_rn(acc.z, acc.w);
        float2 ov;
        ov.x = *(float*)&o0;
        ov.y = *(float*)&o1;
        ((float2*)g_B)[node * 8 + ql] = ov;
    } else {
        int b = __ldg(&batch[node]);
        float* p = &g_pool[b * 32 + 4 * ql];
        atomicAdd(p + 0, acc.x);
        atomicAdd(p + 1, acc.y);
        atomicAdd(p + 2, acc.z);
        atomicAdd(p + 3, acc.w);
        if (ql == 0) atomicAdd(&g_cnt[b], 1);
    }
}

// ---------------- MLP head (single block) -----------------------------------
__global__ void k_mlp(const float* __restrict__ L1w, const float* __restrict__ L1b,
                      const float* __restrict__ L2w, const float* __restrict__ L2b,
                      const float* __restrict__ L3w, const float* __restrict__ L3b,
                      const float* __restrict__ L4w, const float* __restrict__ L4b,
                      float* __restrict__ out) {
    __shared__ float A[GG * MM];
    __shared__ float B[GG * MM];
    int tid = threadIdx.x;  // 256
    for (int i = tid; i < GG * HH; i += 256) {
        int g = i >> 5, f = i & 31;
        float c = (float)g_cnt[g];
        if (c < 1.f) c = 1.f;
        A[g * MM + f] = g_pool[i] / c;
    }
    __syncthreads();
    // L1: 32 -> 64, relu
    for (int i = tid; i < GG * MM; i += 256) {
        int g = i >> 6, m = i & 63;
        float a = L1b[m];
        #pragma unroll
        for (int k = 0; k < HH; k++) a += A[g * MM + k] * L1w[k * MM + m];
        B[g * MM + m] = fmaxf(a, 0.f);
    }
    __syncthreads();
    // L2: 64 -> 64, relu
    for (int i = tid; i < GG * MM; i += 256) {
        int g = i >> 6, m = i & 63;
        float a = L2b[m];
        #pragma unroll
        for (int k = 0; k < MM; k++) a += B[g * MM + k] * L2w[k * MM + m];
        A[g * MM + m] = fmaxf(a, 0.f);
    }
    __syncthreads();
    // L3: 64 -> 64, relu
    for (int i = tid; i < GG * MM; i += 256) {
        int g = i >> 6, m = i & 63;
        float a = L3b[m];
        #pragma unroll
        for (int k = 0; k < MM; k++) a += A[g * MM + k] * L3w[k * MM + m];
        B[g * MM + m] = fmaxf(a, 0.f);
    }
    __syncthreads();
    // L4: 64 -> 10
    for (int i = tid; i < GG * CC; i += 256) {
        int g = i / CC, c = i - g * CC;
        float a = L4b[c];
        #pragma unroll
        for (int k = 0; k < MM; k++) a += B[g * MM + k] * L4w[k * CC + c];
        out[i] = a;
    }
}

// ---------------- launch -----------------------------------------------------
extern "C" void kernel_launch(void* const* d_in, const int* in_sizes, int n_in,
                              void* d_out, int out_size) {
    const float* x    = (const float*)d_in[0];
    const float* ew   = (const float*)d_in[1];
    const float* W1   = (const float*)d_in[2];
    const float* b1   = (const float*)d_in[3];
    const float* W2   = (const float*)d_in[4];
    const float* b2   = (const float*)d_in[5];
    const float* W3   = (const float*)d_in[6];
    const float* b3   = (const float*)d_in[7];
    const float* L1w  = (const float*)d_in[8];
    const float* L1b  = (const float*)d_in[9];
    const float* L2w  = (const float*)d_in[10];
    const float* L2b  = (const float*)d_in[11];
    const float* L3w  = (const float*)d_in[12];
    const float* L3b  = (const float*)d_in[13];
    const float* L4w  = (const float*)d_in[14];
    const float* L4b  = (const float*)d_in[15];
    const int*   ei   = (const int*)d_in[16];   // int32 (JAX x64 disabled)
    const int*   bat  = (const int*)d_in[17];   // int32
    float* out = (float*)d_out;

    const int nb_node  = (NN + 255) / 256;          // 391
    const int nb_vec   = (T4 + 255) / 256;          // 3224
    const int nb_quad  = (NQUAD * 32 + 255) / 256;  // 3125

    k_zero<<<nb_node, 256>>>();
    k_hist<<<nb_vec, 256>>>(ei, ew);
    k_scanA<<<NB, 1024>>>();
    k_scanB<<<1, 128>>>();
    k_scanC<<<NB, 1024>>>();
    k_scatter<<<nb_vec, 256>>>(ei, ew);

    // conv1
    k_gemm128<<<nb_node, 256>>>(x, W1);
    k_agg<<<nb_quad, 256>>>(b1, 1, 0, bat);
    // conv2
    k_gemm32<<<nb_node, 256>>>(W2);
    k_agg<<<nb_quad, 256>>>(b2, 1, 0, bat);
    // conv3
    k_gemm32<<<nb_node, 256>>>(W3);
    k_agg<<<nb_quad, 256>>>(b3, 0, 1, bat);   // fused mean-pool accumulate

    k_mlp<<<1, 256>>>(L1w, L1b, L2w, L2b, L3w, L3b, L4w, L4b, out);
}

// round 10
// speedup vs baseline: 1.0103x; 1.0103x over previous
#include <cuda_runtime.h>
#include <cuda_fp16.h>

#define NN 100000
#define EE 3200000
#define EA 3300000     // EE + NN self loops
#define HH 32
#define MM 64
#define CC 10
#define GG 64
#define NB 98          // ceil(NN / 1024) scan blocks
#define NQUAD 25000    // NN / 4

// ---------------- scratch (device globals; no allocation allowed) ----------
__device__ unsigned long long g_packed[NN];   // (count<<32) | fixedpoint(deg)
__device__ int    g_cursor[NN];
__device__ int    g_rowptr[NN + 1];
__device__ float  g_deg[NN];          // dinv after scanA
__device__ int    g_blocksum[NB];
__device__ int    g_blockoff[NB];
__device__ int2   g_cv[EA];           // per-edge: (src, norm bits), CSR by dst
__device__ __half g_A[NN * HH];       // features fp16, [N][32] (gemm output)
__device__ __half g_B[NN * HH];       // agg output
__device__ float  g_pool[GG * HH];
__device__ int    g_cnt[GG];

// ---------------- init -----------------------------------------------------
__global__ void k_zero() {
    int i = blockIdx.x * blockDim.x + threadIdx.x;
    if (i < NN) g_packed[i] = 0ull;
    if (i < GG * HH) g_pool[i] = 0.f;
    if (i < GG) g_cnt[i] = 0;
}

// ---------------- CSR build (scalar: max TLP for atomic chains) -------------
// one 64-bit atomic per edge: count in hi word, deg (fixed point 2^20) in lo
__global__ void k_hist(const int* __restrict__ ei,
                       const float* __restrict__ ew) {
    int e = blockIdx.x * blockDim.x + threadIdx.x;
    if (e >= EA) return;
    int dst; float w;
    if (e < EE) { dst = ei[EE + e]; w = ew[e]; }
    else        { dst = e - EE;     w = 1.f;   }
    unsigned long long p = (1ull << 32) |
        (unsigned long long)(unsigned)__float2uint_rn(w * 1048576.f);
    atomicAdd(&g_packed[dst], p);
}

// phase A: block-local exclusive scan of counts; fused deg -> dinv
__global__ void __launch_bounds__(1024) k_scanA() {
    __shared__ int wt[32];
    int tid = threadIdx.x;
    int i = blockIdx.x * 1024 + tid;
    unsigned long long p = (i < NN) ? g_packed[i] : 0ull;
    int v = (int)(p >> 32);
    int x = v;
    #pragma unroll
    for (int d = 1; d < 32; d <<= 1) {
        int y = __shfl_up_sync(0xffffffffu, x, d);
        if ((tid & 31) >= d) x += y;
    }
    if ((tid & 31) == 31) wt[tid >> 5] = x;
    __syncthreads();
    if (tid < 32) {
        int t = wt[tid];
        int xx = t;
        #pragma unroll
        for (int d = 1; d < 32; d <<= 1) {
            int y = __shfl_up_sync(0xffffffffu, xx, d);
            if (tid >= d) xx += y;
        }
        wt[tid] = xx - t;   // exclusive warp offsets
    }
    __syncthreads();
    int incl = x + wt[tid >> 5];
    if (i < NN) g_rowptr[i] = incl - v;          // block-local exclusive
    if (tid == 1023) g_blocksum[blockIdx.x] = incl;
    // fused dinv from fixed-point degree
    if (i < NN) {
        float d = (float)(unsigned)(p & 0xffffffffull) * (1.f / 1048576.f);
        g_deg[i] = (d > 0.f) ? rsqrtf(fmaxf(d, 1e-30f)) : 0.f;
    }
}

// phase B: exclusive scan of NB block sums (1 block, 128 threads)
__global__ void k_scanB() {
    __shared__ int wt[4];
    int tid = threadIdx.x;   // 128
    int v = (tid < NB) ? g_blocksum[tid] : 0;
    int x = v;
    #pragma unroll
    for (int d = 1; d < 32; d <<= 1) {
        int y = __shfl_up_sync(0xffffffffu, x, d);
        if ((tid & 31) >= d) x += y;
    }
    if ((tid & 31) == 31) wt[tid >> 5] = x;
    __syncthreads();
    if (tid < 4) {
        int t = wt[tid];
        int xx = t;
        #pragma unroll
        for (int d = 1; d < 4; d <<= 1) {
            int y = __shfl_up_sync(0x0000000fu, xx, d);
            if (tid >= d) xx += y;
        }
        wt[tid] = xx - t;
    }
    __syncthreads();
    int incl = x + wt[tid >> 5];
    if (tid < NB) g_blockoff[tid] = incl - v;
    if (tid == NB - 1) g_rowptr[NN] = incl;
}

// phase C: add block offsets, write final rowptr + cursor
__global__ void __launch_bounds__(1024) k_scanC() {
    int i = blockIdx.x * 1024 + threadIdx.x;
    if (i >= NN) return;
    int out = g_rowptr[i] + g_blockoff[blockIdx.x];
    g_rowptr[i] = out;
    g_cursor[i] = out;
}

__global__ void k_scatter(const int* __restrict__ ei,
                          const float* __restrict__ ew) {
    int e = blockIdx.x * blockDim.x + threadIdx.x;
    if (e >= EA) return;
    int src, dst; float w;
    if (e < EE) { src = ei[e]; dst = ei[EE + e]; w = ew[e]; }
    else        { src = dst = e - EE;            w = 1.f;   }
    float nv = g_deg[src] * w * g_deg[dst];
    int idx = atomicAdd(&g_cursor[dst], 1);
    g_cv[idx] = make_int2(src, __float_as_int(nv));
}

// ---------------- GEMM: g_A[N,32] = X[N,128] @ W[128,32] (fp16 out) ---------
__global__ void __launch_bounds__(256) k_gemm128(const float* __restrict__ X,
                                                 const float* __restrict__ W) {
    __shared__ float4 sW[128 * 8];   // W as [k][o/4]
    __shared__ float  sX[256 * 17];  // 16-wide k-chunk, pad 17
    int tid = threadIdx.x;
    for (int i = tid; i < 1024; i += 256) sW[i] = ((const float4*)W)[i];
    float acc[32];
    #pragma unroll
    for (int o = 0; o < 32; o++) acc[o] = 0.f;
    int row = blockIdx.x * 256 + tid;
    for (int kc = 0; kc < 8; kc++) {
        __syncthreads();
        for (int i = tid; i < 256 * 16; i += 256) {
            int r = i >> 4, c = i & 15;
            int rr = blockIdx.x * 256 + r;
            sX[r * 17 + c] = (rr < NN) ? X[rr * 128 + kc * 16 + c] : 0.f;
        }
        __syncthreads();
        #pragma unroll
        for (int kk = 0; kk < 16; kk++) {
            float xv = sX[tid * 17 + kk];
            int k = kc * 16 + kk;
            #pragma unroll
            for (int o4 = 0; o4 < 8; o4++) {
                float4 wv = sW[k * 8 + o4];
                acc[o4 * 4 + 0] += xv * wv.x;
                acc[o4 * 4 + 1] += xv * wv.y;
                acc[o4 * 4 + 2] += xv * wv.z;
                acc[o4 * 4 + 3] += xv * wv.w;
            }
        }
    }
    if (row < NN) {
        __half2* Y2 = (__half2*)g_A;
        #pragma unroll
        for (int j = 0; j < 16; j++)
            Y2[row * 16 + j] = __floats2half2_rn(acc[2 * j], acc[2 * j + 1]);
    }
}

// ---------------- GEMM32: g_A[N,32] = g_B[N,32] @ W[32,32] ------------------
__global__ void __launch_bounds__(256) k_gemm32(const float* __restrict__ W) {
    __shared__ float4 sW[32 * 8];
    __shared__ float  sX[256 * 33];
    int tid = threadIdx.x;
    for (int i = tid; i < 256; i += 256) sW[i] = ((const float4*)W)[i];
    const __half2* in2 = (const __half2*)g_B;
    for (int i = tid; i < 256 * 16; i += 256) {
        int r = i >> 4, c = i & 15;     // c indexes half2 pairs
        int rr = blockIdx.x * 256 + r;
        float2 v = (rr < NN) ? __half22float2(__ldg(&in2[rr * 16 + c]))
                             : make_float2(0.f, 0.f);
        sX[r * 33 + 2 * c]     = v.x;
        sX[r * 33 + 2 * c + 1] = v.y;
    }
    __syncthreads();
    float acc[32];
    #pragma unroll
    for (int o = 0; o < 32; o++) acc[o] = 0.f;
    #pragma unroll
    for (int kk = 0; kk < 32; kk++) {
        float xv = sX[tid * 33 + kk];
        #pragma unroll
        for (int o4 = 0; o4 < 8; o4++) {
            float4 wv = sW[kk * 8 + o4];
            acc[o4 * 4 + 0] += xv * wv.x;
            acc[o4 * 4 + 1] += xv * wv.y;
            acc[o4 * 4 + 2] += xv * wv.z;
            acc[o4 * 4 + 3] += xv * wv.w;
        }
    }
    int row = blockIdx.x * 256 + tid;
    if (row < NN) {
        __half2* Y2 = (__half2*)g_A;
        #pragma unroll
        for (int j = 0; j < 16; j++)
            Y2[row * 16 + j] = __floats2half2_rn(acc[2 * j], acc[2 * j + 1]);
    }
}

// ---------------- edge aggregation: agg(g_A) --------------------------------
// 4 nodes per warp: quarter-warp (8 lanes) per node, lane covers 4 features.
// mode 0: write g_B; mode 1: mean-pool atomics (epilogue only differs).
__global__ void __launch_bounds__(256) k_agg(const float* __restrict__ bias,
                                             int relu, int mode,
                                             const int* __restrict__ batch) {
    int quad = (blockIdx.x * blockDim.x + threadIdx.x) >> 5;
    if (quad >= NQUAD) return;
    int lane = threadIdx.x & 31;
    int q  = lane >> 3;            // node within quad (0..3)
    int ql = lane & 7;             // feature group: features 4*ql .. 4*ql+3
    int node = quad * 4 + q;
    int beg = g_rowptr[node], end = g_rowptr[node + 1];
    int myc = end - beg;
    // max degree across the 4 nodes of this warp
    int m1 = __shfl_xor_sync(0xffffffffu, myc, 8);
    int mx = (myc > m1) ? myc : m1;
    int m2 = __shfl_xor_sync(0xffffffffu, mx, 16);
    int maxit = (mx > m2) ? mx : m2;
    const float2* __restrict__ in2 = (const float2*)g_A;   // 8B = 4 halves
    float4 acc = make_float4(0.f, 0.f, 0.f, 0.f);
    #pragma unroll 4
    for (int it = 0; it < maxit; it++) {
        int e = beg + it;
        if (e < end) {
            int2 cv = __ldg(&g_cv[e]);
            float nv = __int_as_float(cv.y);
            float2 packed = __ldg(&in2[cv.x * 8 + ql]);
            float2 h01 = __half22float2(*(const __half2*)&packed.x);
            float2 h23 = __half22float2(*(const __half2*)&packed.y);
            acc.x += nv * h01.x;
            acc.y += nv * h01.y;
            acc.z += nv * h23.x;
            acc.w += nv * h23.y;
        }
    }
    float4 bv = __ldg(&((const float4*)bias)[ql]);
    acc.x += bv.x; acc.y += bv.y; acc.z += bv.z; acc.w += bv.w;
    if (relu) {
        acc.x = fmaxf(acc.x, 0.f);
        acc.y = fmaxf(acc.y, 0.f);
        acc.z = fmaxf(acc.z, 0.f);
        acc.w = fmaxf(acc.w, 0.f);
    }
    if (mode == 0) {
        __half2 o0 = __floats2half2_rn(acc.x, acc.y);
        __half2 o1 = __floats2half2_rn(acc.z, acc.w);
        float2 ov;
        ov.x = *(float*)&o0;
        ov.y = *(float*)&o1;
        ((float2*)g_B)[node * 8 + ql] = ov;
    } else {
        int b = __ldg(&batch[node]);
        float* p = &g_pool[b * 32 + 4 * ql];
        atomicAdd(p + 0, acc.x);
        atomicAdd(p + 1, acc.y);
        atomicAdd(p + 2, acc.z);
        atomicAdd(p + 3, acc.w);
        if (ql == 0) atomicAdd(&g_cnt[b], 1);
    }
}

// ---------------- MLP head (single block) -----------------------------------
__global__ void k_mlp(const float* __restrict__ L1w, const float* __restrict__ L1b,
                      const float* __restrict__ L2w, const float* __restrict__ L2b,
                      const float* __restrict__ L3w, const float* __restrict__ L3b,
                      const float* __restrict__ L4w, const float* __restrict__ L4b,
                      float* __restrict__ out) {
    __shared__ float A[GG * MM];
    __shared__ float B[GG * MM];
    int tid = threadIdx.x;  // 256
    for (int i = tid; i < GG * HH; i += 256) {
        int g = i >> 5, f = i & 31;
        float c = (float)g_cnt[g];
        if (c < 1.f) c = 1.f;
        A[g * MM + f] = g_pool[i] / c;
    }
    __syncthreads();
    // L1: 32 -> 64, relu
    for (int i = tid; i < GG * MM; i += 256) {
        int g = i >> 6, m = i & 63;
        float a = L1b[m];
        #pragma unroll
        for (int k = 0; k < HH; k++) a += A[g * MM + k] * L1w[k * MM + m];
        B[g * MM + m] = fmaxf(a, 0.f);
    }
    __syncthreads();
    // L2: 64 -> 64, relu
    for (int i = tid; i < GG * MM; i += 256) {
        int g = i >> 6, m = i & 63;
        float a = L2b[m];
        #pragma unroll
        for (int k = 0; k < MM; k++) a += B[g * MM + k] * L2w[k * MM + m];
        A[g * MM + m] = fmaxf(a, 0.f);
    }
    __syncthreads();
    // L3: 64 -> 64, relu
    for (int i = tid; i < GG * MM; i += 256) {
        int g = i >> 6, m = i & 63;
        float a = L3b[m];
        #pragma unroll
        for (int k = 0; k < MM; k++) a += A[g * MM + k] * L3w[k * MM + m];
        B[g * MM + m] = fmaxf(a, 0.f);
    }
    __syncthreads();
    // L4: 64 -> 10
    for (int i = tid; i < GG * CC; i += 256) {
        int g = i / CC, c = i - g * CC;
        float a = L4b[c];
        #pragma unroll
        for (int k = 0; k < MM; k++) a += B[g * MM + k] * L4w[k * CC + c];
        out[i] = a;
    }
}

// ---------------- launch -----------------------------------------------------
extern "C" void kernel_launch(void* const* d_in, const int* in_sizes, int n_in,
                              void* d_out, int out_size) {
    const float* x    = (const float*)d_in[0];
    const float* ew   = (const float*)d_in[1];
    const float* W1   = (const float*)d_in[2];
    const float* b1   = (const float*)d_in[3];
    const float* W2   = (const float*)d_in[4];
    const float* b2   = (const float*)d_in[5];
    const float* W3   = (const float*)d_in[6];
    const float* b3   = (const float*)d_in[7];
    const float* L1w  = (const float*)d_in[8];
    const float* L1b  = (const float*)d_in[9];
    const float* L2w  = (const float*)d_in[10];
    const float* L2b  = (const float*)d_in[11];
    const float* L3w  = (const float*)d_in[12];
    const float* L3b  = (const float*)d_in[13];
    const float* L4w  = (const float*)d_in[14];
    const float* L4b  = (const float*)d_in[15];
    const int*   ei   = (const int*)d_in[16];   // int32 (JAX x64 disabled)
    const int*   bat  = (const int*)d_in[17];   // int32
    float* out = (float*)d_out;

    const int nb_node  = (NN + 255) / 256;          // 391
    const int nb_edge  = (EA + 255) / 256;          // 12891
    const int nb_quad  = (NQUAD * 32 + 255) / 256;  // 3125

    k_zero<<<nb_node, 256>>>();
    k_hist<<<nb_edge, 256>>>(ei, ew);
    k_scanA<<<NB, 1024>>>();
    k_scanB<<<1, 128>>>();
    k_scanC<<<NB, 1024>>>();
    k_scatter<<<nb_edge, 256>>>(ei, ew);

    // conv1
    k_gemm128<<<nb_node, 256>>>(x, W1);
    k_agg<<<nb_quad, 256>>>(b1, 1, 0, bat);
    // conv2
    k_gemm32<<<nb_node, 256>>>(W2);
    k_agg<<<nb_quad, 256>>>(b2, 1, 0, bat);
    // conv3
    k_gemm32<<<nb_node, 256>>>(W3);
    k_agg<<<nb_quad, 256>>>(b3, 0, 1, bat);   // fused mean-pool accumulate

    k_mlp<<<1, 256>>>(L1w, L1b, L2w, L2b, L3w, L3b, L4w, L4b, out);
}

// round 11
// speedup vs baseline: 1.2735x; 1.2606x over previous
#include <cuda_runtime.h>
#include <cuda_fp16.h>

#define NN 100000
#define EE 3200000
#define EA 3300000     // EE + NN self loops
#define HH 32
#define MM 64
#define CC 10
#define GG 64
#define NB 98          // ceil(NN / 1024) scan blocks
#define NQUAD 25000    // NN / 4

// ---------------- scratch (device globals; no allocation allowed) ----------
__device__ unsigned long long g_packed[NN];   // (count<<32) | fixedpoint(deg)
__device__ int    g_cursor[NN];
__device__ int    g_rowptr[NN + 1];
__device__ float  g_deg[NN];          // dinv after scanA
__device__ int    g_blocksum[NB];
__device__ int    g_blockoff[NB];
__device__ int2   g_cv[EA];           // per-edge: (src, raw weight), CSR by dst
__device__ __half g_A[NN * HH];       // dinv-scaled features fp16 (gemm out)
__device__ __half g_B[NN * HH];       // conv output (agg out)
__device__ float  g_pool[GG * HH];
__device__ int    g_cnt[GG];

// ---------------- init -----------------------------------------------------
__global__ void k_zero() {
    int i = blockIdx.x * blockDim.x + threadIdx.x;
    if (i < NN) g_packed[i] = 0ull;
    if (i < GG * HH) g_pool[i] = 0.f;
    if (i < GG) g_cnt[i] = 0;
}

// ---------------- CSR build (scalar: max TLP for atomic chains) -------------
// one 64-bit atomic per edge: count in hi word, deg (fixed point 2^20) in lo
__global__ void k_hist(const int* __restrict__ ei,
                       const float* __restrict__ ew) {
    int e = blockIdx.x * blockDim.x + threadIdx.x;
    if (e >= EA) return;
    int dst; float w;
    if (e < EE) { dst = ei[EE + e]; w = ew[e]; }
    else        { dst = e - EE;     w = 1.f;   }
    unsigned long long p = (1ull << 32) |
        (unsigned long long)(unsigned)__float2uint_rn(w * 1048576.f);
    atomicAdd(&g_packed[dst], p);
}

// phase A: block-local exclusive scan of counts; fused deg -> dinv
__global__ void __launch_bounds__(1024) k_scanA() {
    __shared__ int wt[32];
    int tid = threadIdx.x;
    int i = blockIdx.x * 1024 + tid;
    unsigned long long p = (i < NN) ? g_packed[i] : 0ull;
    int v = (int)(p >> 32);
    int x = v;
    #pragma unroll
    for (int d = 1; d < 32; d <<= 1) {
        int y = __shfl_up_sync(0xffffffffu, x, d);
        if ((tid & 31) >= d) x += y;
    }
    if ((tid & 31) == 31) wt[tid >> 5] = x;
    __syncthreads();
    if (tid < 32) {
        int t = wt[tid];
        int xx = t;
        #pragma unroll
        for (int d = 1; d < 32; d <<= 1) {
            int y = __shfl_up_sync(0xffffffffu, xx, d);
            if (tid >= d) xx += y;
        }
        wt[tid] = xx - t;   // exclusive warp offsets
    }
    __syncthreads();
    int incl = x + wt[tid >> 5];
    if (i < NN) g_rowptr[i] = incl - v;          // block-local exclusive
    if (tid == 1023) g_blocksum[blockIdx.x] = incl;
    // fused dinv from fixed-point degree
    if (i < NN) {
        float d = (float)(unsigned)(p & 0xffffffffull) * (1.f / 1048576.f);
        g_deg[i] = (d > 0.f) ? rsqrtf(fmaxf(d, 1e-30f)) : 0.f;
    }
}

// phase B: exclusive scan of NB block sums (1 block, 128 threads)
__global__ void k_scanB() {
    __shared__ int wt[4];
    int tid = threadIdx.x;   // 128
    int v = (tid < NB) ? g_blocksum[tid] : 0;
    int x = v;
    #pragma unroll
    for (int d = 1; d < 32; d <<= 1) {
        int y = __shfl_up_sync(0xffffffffu, x, d);
        if ((tid & 31) >= d) x += y;
    }
    if ((tid & 31) == 31) wt[tid >> 5] = x;
    __syncthreads();
    if (tid < 4) {
        int t = wt[tid];
        int xx = t;
        #pragma unroll
        for (int d = 1; d < 4; d <<= 1) {
            int y = __shfl_up_sync(0x0000000fu, xx, d);
            if (tid >= d) xx += y;
        }
        wt[tid] = xx - t;
    }
    __syncthreads();
    int incl = x + wt[tid >> 5];
    if (tid < NB) g_blockoff[tid] = incl - v;
    if (tid == NB - 1) g_rowptr[NN] = incl;
}

// phase C: add block offsets, write final rowptr + cursor
__global__ void __launch_bounds__(1024) k_scanC() {
    int i = blockIdx.x * 1024 + threadIdx.x;
    if (i >= NN) return;
    int out = g_rowptr[i] + g_blockoff[blockIdx.x];
    g_rowptr[i] = out;
    g_cursor[i] = out;
}

// scatter stores RAW weight (no g_deg loads; dinv folded into features)
__global__ void k_scatter(const int* __restrict__ ei,
                          const float* __restrict__ ew) {
    int e = blockIdx.x * blockDim.x + threadIdx.x;
    if (e >= EA) return;
    int src, dst; float w;
    if (e < EE) { src = ei[e]; dst = ei[EE + e]; w = ew[e]; }
    else        { src = dst = e - EE;            w = 1.f;   }
    int idx = atomicAdd(&g_cursor[dst], 1);
    g_cv[idx] = make_int2(src, __float_as_int(w));
}

// ---------------- GEMM: g_A[N,32] = dinv * (X[N,128] @ W[128,32]) -----------
__global__ void __launch_bounds__(256) k_gemm128(const float* __restrict__ X,
                                                 const float* __restrict__ W) {
    __shared__ float4 sW[128 * 8];   // W as [k][o/4]
    __shared__ float  sX[256 * 17];  // 16-wide k-chunk, pad 17
    int tid = threadIdx.x;
    for (int i = tid; i < 1024; i += 256) sW[i] = ((const float4*)W)[i];
    float acc[32];
    #pragma unroll
    for (int o = 0; o < 32; o++) acc[o] = 0.f;
    int row = blockIdx.x * 256 + tid;
    for (int kc = 0; kc < 8; kc++) {
        __syncthreads();
        for (int i = tid; i < 256 * 16; i += 256) {
            int r = i >> 4, c = i & 15;
            int rr = blockIdx.x * 256 + r;
            sX[r * 17 + c] = (rr < NN) ? X[rr * 128 + kc * 16 + c] : 0.f;
        }
        __syncthreads();
        #pragma unroll
        for (int kk = 0; kk < 16; kk++) {
            float xv = sX[tid * 17 + kk];
            int k = kc * 16 + kk;
            #pragma unroll
            for (int o4 = 0; o4 < 8; o4++) {
                float4 wv = sW[k * 8 + o4];
                acc[o4 * 4 + 0] += xv * wv.x;
                acc[o4 * 4 + 1] += xv * wv.y;
                acc[o4 * 4 + 2] += xv * wv.z;
                acc[o4 * 4 + 3] += xv * wv.w;
            }
        }
    }
    if (row < NN) {
        float dv = __ldg(&g_deg[row]);
        __half2* Y2 = (__half2*)g_A;
        #pragma unroll
        for (int j = 0; j < 16; j++)
            Y2[row * 16 + j] = __floats2half2_rn(dv * acc[2 * j], dv * acc[2 * j + 1]);
    }
}

// ---------------- GEMM32: g_A[N,32] = dinv * (g_B[N,32] @ W[32,32]) ---------
__global__ void __launch_bounds__(256) k_gemm32(const float* __restrict__ W) {
    __shared__ float4 sW[32 * 8];
    __shared__ float  sX[256 * 33];
    int tid = threadIdx.x;
    for (int i = tid; i < 256; i += 256) sW[i] = ((const float4*)W)[i];
    const __half2* in2 = (const __half2*)g_B;
    for (int i = tid; i < 256 * 16; i += 256) {
        int r = i >> 4, c = i & 15;     // c indexes half2 pairs
        int rr = blockIdx.x * 256 + r;
        float2 v = (rr < NN) ? __half22float2(__ldg(&in2[rr * 16 + c]))
                             : make_float2(0.f, 0.f);
        sX[r * 33 + 2 * c]     = v.x;
        sX[r * 33 + 2 * c + 1] = v.y;
    }
    __syncthreads();
    float acc[32];
    #pragma unroll
    for (int o = 0; o < 32; o++) acc[o] = 0.f;
    #pragma unroll
    for (int kk = 0; kk < 32; kk++) {
        float xv = sX[tid * 33 + kk];
        #pragma unroll
        for (int o4 = 0; o4 < 8; o4++) {
            float4 wv = sW[kk * 8 + o4];
            acc[o4 * 4 + 0] += xv * wv.x;
            acc[o4 * 4 + 1] += xv * wv.y;
            acc[o4 * 4 + 2] += xv * wv.z;
            acc[o4 * 4 + 3] += xv * wv.w;
        }
    }
    int row = blockIdx.x * 256 + tid;
    if (row < NN) {
        float dv = __ldg(&g_deg[row]);
        __half2* Y2 = (__half2*)g_A;
        #pragma unroll
        for (int j = 0; j < 16; j++)
            Y2[row * 16 + j] = __floats2half2_rn(dv * acc[2 * j], dv * acc[2 * j + 1]);
    }
}

// ---------------- edge aggregation: g_B = dinv*agg(g_A) + b -----------------
// 4 nodes per warp: quarter-warp (8 lanes) per node, lane covers 4 features.
__global__ void __launch_bounds__(256) k_agg(const float* __restrict__ bias,
                                             int relu) {
    int quad = (blockIdx.x * blockDim.x + threadIdx.x) >> 5;
    if (quad >= NQUAD) return;
    int lane = threadIdx.x & 31;
    int q  = lane >> 3;            // node within quad (0..3)
    int ql = lane & 7;             // feature group: features 4*ql .. 4*ql+3
    int node = quad * 4 + q;
    int beg = g_rowptr[node], end = g_rowptr[node + 1];
    int myc = end - beg;
    // max degree across the 4 nodes of this warp
    int m1 = __shfl_xor_sync(0xffffffffu, myc, 8);
    int mx = (myc > m1) ? myc : m1;
    int m2 = __shfl_xor_sync(0xffffffffu, mx, 16);
    int maxit = (mx > m2) ? mx : m2;
    const float2* __restrict__ in2 = (const float2*)g_A;   // 8B = 4 halves
    float4 acc = make_float4(0.f, 0.f, 0.f, 0.f);
    #pragma unroll 4
    for (int it = 0; it < maxit; it++) {
        int e = beg + it;
        if (e < end) {
            int2 cv = __ldg(&g_cv[e]);
            float nv = __int_as_float(cv.y);
            float2 packed = __ldg(&in2[cv.x * 8 + ql]);
            float2 h01 = __half22float2(*(const __half2*)&packed.x);
            float2 h23 = __half22float2(*(const __half2*)&packed.y);
            acc.x += nv * h01.x;
            acc.y += nv * h01.y;
            acc.z += nv * h23.x;
            acc.w += nv * h23.y;
        }
    }
    float dinv = __ldg(&g_deg[node]);
    float4 bv = __ldg(&((const float4*)bias)[ql]);
    acc.x = dinv * acc.x + bv.x;
    acc.y = dinv * acc.y + bv.y;
    acc.z = dinv * acc.z + bv.z;
    acc.w = dinv * acc.w + bv.w;
    if (relu) {
        acc.x = fmaxf(acc.x, 0.f);
        acc.y = fmaxf(acc.y, 0.f);
        acc.z = fmaxf(acc.z, 0.f);
        acc.w = fmaxf(acc.w, 0.f);
    }
    __half2 o0 = __floats2half2_rn(acc.x, acc.y);
    __half2 o1 = __floats2half2_rn(acc.z, acc.w);
    float2 ov;
    ov.x = *(float*)&o0;
    ov.y = *(float*)&o1;
    ((float2*)g_B)[node * 8 + ql] = ov;
}

// ---------------- mean pool (reads g_B fp16) --------------------------------
__global__ void k_pool(const int* __restrict__ batch) {
    int i = blockIdx.x * blockDim.x + threadIdx.x;
    if (i >= NN * 32) return;
    int n = i >> 5, f = i & 31;
    int b = batch[n];
    atomicAdd(&g_pool[b * 32 + f], __half2float(g_B[i]));
    if (f == 0) atomicAdd(&g_cnt[b], 1);
}

// ---------------- MLP head (single block) -----------------------------------
__global__ void k_mlp(const float* __restrict__ L1w, const float* __restrict__ L1b,
                      const float* __restrict__ L2w, const float* __restrict__ L2b,
                      const float* __restrict__ L3w, const float* __restrict__ L3b,
                      const float* __restrict__ L4w, const float* __restrict__ L4b,
                      float* __restrict__ out) {
    __shared__ float A[GG * MM];
    __shared__ float B[GG * MM];
    int tid = threadIdx.x;  // 256
    for (int i = tid; i < GG * HH; i += 256) {
        int g = i >> 5, f = i & 31;
        float c = (float)g_cnt[g];
        if (c < 1.f) c = 1.f;
        A[g * MM + f] = g_pool[i] / c;
    }
    __syncthreads();
    // L1: 32 -> 64, relu
    for (int i = tid; i < GG * MM; i += 256) {
        int g = i >> 6, m = i & 63;
        float a = L1b[m];
        #pragma unroll
        for (int k = 0; k < HH; k++) a += A[g * MM + k] * L1w[k * MM + m];
        B[g * MM + m] = fmaxf(a, 0.f);
    }
    __syncthreads();
    // L2: 64 -> 64, relu
    for (int i = tid; i < GG * MM; i += 256) {
        int g = i >> 6, m = i & 63;
        float a = L2b[m];
        #pragma unroll
        for (int k = 0; k < MM; k++) a += B[g * MM + k] * L2w[k * MM + m];
        A[g * MM + m] = fmaxf(a, 0.f);
    }
    __syncthreads();
    // L3: 64 -> 64, relu
    for (int i = tid; i < GG * MM; i += 256) {
        int g = i >> 6, m = i & 63;
        float a = L3b[m];
        #pragma unroll
        for (int k = 0; k < MM; k++) a += A[g * MM + k] * L3w[k * MM + m];
        B[g * MM + m] = fmaxf(a, 0.f);
    }
    __syncthreads();
    // L4: 64 -> 10
    for (int i = tid; i < GG * CC; i += 256) {
        int g = i / CC, c = i - g * CC;
        float a = L4b[c];
        #pragma unroll
        for (int k = 0; k < MM; k++) a += B[g * MM + k] * L4w[k * CC + c];
        out[i] = a;
    }
}

// ---------------- launch -----------------------------------------------------
extern "C" void kernel_launch(void* const* d_in, const int* in_sizes, int n_in,
                              void* d_out, int out_size) {
    const float* x    = (const float*)d_in[0];
    const float* ew   = (const float*)d_in[1];
    const float* W1   = (const float*)d_in[2];
    const float* b1   = (const float*)d_in[3];
    const float* W2   = (const float*)d_in[4];
    const float* b2   = (const float*)d_in[5];
    const float* W3   = (const float*)d_in[6];
    const float* b3   = (const float*)d_in[7];
    const float* L1w  = (const float*)d_in[8];
    const float* L1b  = (const float*)d_in[9];
    const float* L2w  = (const float*)d_in[10];
    const float* L2b  = (const float*)d_in[11];
    const float* L3w  = (const float*)d_in[12];
    const float* L3b  = (const float*)d_in[13];
    const float* L4w  = (const float*)d_in[14];
    const float* L4b  = (const float*)d_in[15];
    const int*   ei   = (const int*)d_in[16];   // int32 (JAX x64 disabled)
    const int*   bat  = (const int*)d_in[17];   // int32
    float* out = (float*)d_out;

    const int nb_node  = (NN + 255) / 256;          // 391
    const int nb_edge  = (EA + 255) / 256;          // 12891
    const int nb_quad  = (NQUAD * 32 + 255) / 256;  // 3125
    const int nb_nwarp = (NN * 32 + 255) / 256;     // 12500

    k_zero<<<nb_node, 256>>>();
    k_hist<<<nb_edge, 256>>>(ei, ew);
    k_scanA<<<NB, 1024>>>();
    k_scanB<<<1, 128>>>();
    k_scanC<<<NB, 1024>>>();
    k_scatter<<<nb_edge, 256>>>(ei, ew);

    // conv1
    k_gemm128<<<nb_node, 256>>>(x, W1);
    k_agg<<<nb_quad, 256>>>(b1, 1);
    // conv2
    k_gemm32<<<nb_node, 256>>>(W2);
    k_agg<<<nb_quad, 256>>>(b2, 1);
    // conv3
    k_gemm32<<<nb_node, 256>>>(W3);
    k_agg<<<nb_quad, 256>>>(b3, 0);

    k_pool<<<nb_nwarp, 256>>>(bat);
    k_mlp<<<1, 256>>>(L1w, L1b, L2w, L2b, L3w, L3b, L4w, L4b, out);
}

// round 12
// speedup vs baseline: 1.4665x; 1.1515x over previous
#include <cuda_runtime.h>
#include <cuda_fp16.h>

#define NN 100000
#define EE 3200000
#define EA 3300000     // EE + NN self loops
#define HH 32
#define MM 64
#define CC 10
#define GG 64
#define NB 98          // ceil(NN / 1024) scan blocks
#define NQUAD 25000    // NN / 4

// ---------------- scratch (device globals; no allocation allowed) ----------
__device__ unsigned long long g_packed[NN];   // (count<<32) | fixedpoint(deg)
__device__ int    g_cursor[NN];
__device__ int    g_rowptr[NN + 1];
__device__ float  g_deg[NN];          // dinv after scanA
__device__ int    g_blocksum[NB];
__device__ int    g_blockoff[NB];
__device__ int2   g_cv[EA];           // per-edge: (src, raw weight), CSR by dst
__device__ __half g_A[NN * HH];       // dinv-scaled features fp16 (gemm out)
__device__ __half g_B[NN * HH];       // conv output (agg out)
__device__ float  g_pool[GG * HH];
__device__ int    g_cnt[GG];

// ---------------- init -----------------------------------------------------
__global__ void k_zero() {
    int i = blockIdx.x * blockDim.x + threadIdx.x;
    if (i < NN) g_packed[i] = 0ull;
    if (i < GG * HH) g_pool[i] = 0.f;
    if (i < GG) g_cnt[i] = 0;
}

// ---------------- CSR build (scalar: max TLP for atomic chains) -------------
__global__ void k_hist(const int* __restrict__ ei,
                       const float* __restrict__ ew) {
    int e = blockIdx.x * blockDim.x + threadIdx.x;
    if (e >= EA) return;
    int dst; float w;
    if (e < EE) { dst = ei[EE + e]; w = ew[e]; }
    else        { dst = e - EE;     w = 1.f;   }
    unsigned long long p = (1ull << 32) |
        (unsigned long long)(unsigned)__float2uint_rn(w * 1048576.f);
    atomicAdd(&g_packed[dst], p);
}

// phase A: block-local exclusive scan of counts; fused deg -> dinv
__global__ void __launch_bounds__(1024) k_scanA() {
    __shared__ int wt[32];
    int tid = threadIdx.x;
    int i = blockIdx.x * 1024 + tid;
    unsigned long long p = (i < NN) ? g_packed[i] : 0ull;
    int v = (int)(p >> 32);
    int x = v;
    #pragma unroll
    for (int d = 1; d < 32; d <<= 1) {
        int y = __shfl_up_sync(0xffffffffu, x, d);
        if ((tid & 31) >= d) x += y;
    }
    if ((tid & 31) == 31) wt[tid >> 5] = x;
    __syncthreads();
    if (tid < 32) {
        int t = wt[tid];
        int xx = t;
        #pragma unroll
        for (int d = 1; d < 32; d <<= 1) {
            int y = __shfl_up_sync(0xffffffffu, xx, d);
            if (tid >= d) xx += y;
        }
        wt[tid] = xx - t;   // exclusive warp offsets
    }
    __syncthreads();
    int incl = x + wt[tid >> 5];
    if (i < NN) g_rowptr[i] = incl - v;          // block-local exclusive
    if (tid == 1023) g_blocksum[blockIdx.x] = incl;
    if (i < NN) {
        float d = (float)(unsigned)(p & 0xffffffffull) * (1.f / 1048576.f);
        g_deg[i] = (d > 0.f) ? rsqrtf(fmaxf(d, 1e-30f)) : 0.f;
    }
}

// phase B: exclusive scan of NB block sums (1 block, 128 threads)
__global__ void k_scanB() {
    __shared__ int wt[4];
    int tid = threadIdx.x;   // 128
    int v = (tid < NB) ? g_blocksum[tid] : 0;
    int x = v;
    #pragma unroll
    for (int d = 1; d < 32; d <<= 1) {
        int y = __shfl_up_sync(0xffffffffu, x, d);
        if ((tid & 31) >= d) x += y;
    }
    if ((tid & 31) == 31) wt[tid >> 5] = x;
    __syncthreads();
    if (tid < 4) {
        int t = wt[tid];
        int xx = t;
        #pragma unroll
        for (int d = 1; d < 4; d <<= 1) {
            int y = __shfl_up_sync(0x0000000fu, xx, d);
            if (tid >= d) xx += y;
        }
        wt[tid] = xx - t;
    }
    __syncthreads();
    int incl = x + wt[tid >> 5];
    if (tid < NB) g_blockoff[tid] = incl - v;
    if (tid == NB - 1) g_rowptr[NN] = incl;
}

// phase C: add block offsets, write final rowptr + cursor
__global__ void __launch_bounds__(1024) k_scanC() {
    int i = blockIdx.x * 1024 + threadIdx.x;
    if (i >= NN) return;
    int out = g_rowptr[i] + g_blockoff[blockIdx.x];
    g_rowptr[i] = out;
    g_cursor[i] = out;
}

// scatter stores RAW weight (no g_deg loads; dinv folded into features)
__global__ void k_scatter(const int* __restrict__ ei,
                          const float* __restrict__ ew) {
    int e = blockIdx.x * blockDim.x + threadIdx.x;
    if (e >= EA) return;
    int src, dst; float w;
    if (e < EE) { src = ei[e]; dst = ei[EE + e]; w = ew[e]; }
    else        { src = dst = e - EE;            w = 1.f;   }
    int idx = atomicAdd(&g_cursor[dst], 1);
    g_cv[idx] = make_int2(src, __float_as_int(w));
}

// ---------------- GEMM: g_A[N,32] = dinv * (X[N,128] @ W[128,32]) -----------
// Transposed sX[k][row]; thread = (rowgroup rg of 4 rows) x (outgroup og of 8).
// Inner loop: 3 LDS.128 per 32 FMA -> FMA-bound.
__global__ void __launch_bounds__(256) k_gemm128(const float* __restrict__ X,
                                                 const float* __restrict__ W) {
    __shared__ float4 sW[128 * 8];    // W as [k][o/4]
    __shared__ float  sX[16][260];    // [k-chunk][row], pad 260 (16B-aligned rows)
    int tid = threadIdx.x;
    int rg = tid >> 2;                // 0..63
    int og = tid & 3;                 // 0..3
    int rowbase = blockIdx.x * 256;
    for (int i = tid; i < 1024; i += 256) sW[i] = ((const float4*)W)[i];
    float acc[4][8];
    #pragma unroll
    for (int r = 0; r < 4; r++)
        #pragma unroll
        for (int o = 0; o < 8; o++) acc[r][o] = 0.f;
    for (int kc = 0; kc < 8; kc++) {
        __syncthreads();
        {
            int r = tid >> 4, c = tid & 15;     // 16 rows per pass
            #pragma unroll
            for (int rp = 0; rp < 16; rp++) {
                int rr = rowbase + r;
                sX[c][r] = (rr < NN) ? X[rr * 128 + kc * 16 + c] : 0.f;
                r += 16;
            }
        }
        __syncthreads();
        #pragma unroll
        for (int kk = 0; kk < 16; kk++) {
            float4 xv = *(const float4*)&sX[kk][rg * 4];
            int k = kc * 16 + kk;
            float4 w0 = sW[k * 8 + og * 2];
            float4 w1 = sW[k * 8 + og * 2 + 1];
            float xr[4] = {xv.x, xv.y, xv.z, xv.w};
            #pragma unroll
            for (int r = 0; r < 4; r++) {
                acc[r][0] += xr[r] * w0.x;
                acc[r][1] += xr[r] * w0.y;
                acc[r][2] += xr[r] * w0.z;
                acc[r][3] += xr[r] * w0.w;
                acc[r][4] += xr[r] * w1.x;
                acc[r][5] += xr[r] * w1.y;
                acc[r][6] += xr[r] * w1.z;
                acc[r][7] += xr[r] * w1.w;
            }
        }
    }
    #pragma unroll
    for (int r = 0; r < 4; r++) {
        int row = rowbase + rg * 4 + r;
        if (row < NN) {
            float dv = __ldg(&g_deg[row]);
            __half2 h0 = __floats2half2_rn(dv * acc[r][0], dv * acc[r][1]);
            __half2 h1 = __floats2half2_rn(dv * acc[r][2], dv * acc[r][3]);
            __half2 h2 = __floats2half2_rn(dv * acc[r][4], dv * acc[r][5]);
            __half2 h3 = __floats2half2_rn(dv * acc[r][6], dv * acc[r][7]);
            float4 ov;
            ov.x = *(float*)&h0; ov.y = *(float*)&h1;
            ov.z = *(float*)&h2; ov.w = *(float*)&h3;
            ((float4*)g_A)[row * 4 + og] = ov;
        }
    }
}

// ---------------- GEMM32: g_A[N,32] = dinv * (g_B[N,32] @ W[32,32]) ---------
__global__ void __launch_bounds__(256) k_gemm32(const float* __restrict__ W) {
    __shared__ float4 sW[32 * 8];
    __shared__ float  sX[32][260];    // [k][row]
    int tid = threadIdx.x;
    int rg = tid >> 2;
    int og = tid & 3;
    int rowbase = blockIdx.x * 256;
    for (int i = tid; i < 256; i += 256) sW[i] = ((const float4*)W)[i];
    const __half2* in2 = (const __half2*)g_B;
    {
        int r = tid >> 4, c = tid & 15;     // c = half2 index
        #pragma unroll
        for (int rp = 0; rp < 16; rp++) {
            int rr = rowbase + r;
            float2 v = (rr < NN) ? __half22float2(__ldg(&in2[rr * 16 + c]))
                                 : make_float2(0.f, 0.f);
            sX[2 * c][r]     = v.x;
            sX[2 * c + 1][r] = v.y;
            r += 16;
        }
    }
    __syncthreads();
    float acc[4][8];
    #pragma unroll
    for (int r = 0; r < 4; r++)
        #pragma unroll
        for (int o = 0; o < 8; o++) acc[r][o] = 0.f;
    #pragma unroll
    for (int kk = 0; kk < 32; kk++) {
        float4 xv = *(const float4*)&sX[kk][rg * 4];
        float4 w0 = sW[kk * 8 + og * 2];
        float4 w1 = sW[kk * 8 + og * 2 + 1];
        float xr[4] = {xv.x, xv.y, xv.z, xv.w};
        #pragma unroll
        for (int r = 0; r < 4; r++) {
            acc[r][0] += xr[r] * w0.x;
            acc[r][1] += xr[r] * w0.y;
            acc[r][2] += xr[r] * w0.z;
            acc[r][3] += xr[r] * w0.w;
            acc[r][4] += xr[r] * w1.x;
            acc[r][5] += xr[r] * w1.y;
            acc[r][6] += xr[r] * w1.z;
            acc[r][7] += xr[r] * w1.w;
        }
    }
    #pragma unroll
    for (int r = 0; r < 4; r++) {
        int row = rowbase + rg * 4 + r;
        if (row < NN) {
            float dv = __ldg(&g_deg[row]);
            __half2 h0 = __floats2half2_rn(dv * acc[r][0], dv * acc[r][1]);
            __half2 h1 = __floats2half2_rn(dv * acc[r][2], dv * acc[r][3]);
            __half2 h2 = __floats2half2_rn(dv * acc[r][4], dv * acc[r][5]);
            __half2 h3 = __floats2half2_rn(dv * acc[r][6], dv * acc[r][7]);
            float4 ov;
            ov.x = *(float*)&h0; ov.y = *(float*)&h1;
            ov.z = *(float*)&h2; ov.w = *(float*)&h3;
            ((float4*)g_A)[row * 4 + og] = ov;
        }
    }
}

// ---------------- edge aggregation: g_B = dinv*agg(g_A) + b -----------------
// 4 nodes per warp: quarter-warp (8 lanes) per node, lane covers 4 features.
__global__ void __launch_bounds__(256) k_agg(const float* __restrict__ bias,
                                             int relu) {
    int quad = (blockIdx.x * blockDim.x + threadIdx.x) >> 5;
    if (quad >= NQUAD) return;
    int lane = threadIdx.x & 31;
    int q  = lane >> 3;            // node within quad (0..3)
    int ql = lane & 7;             // feature group: features 4*ql .. 4*ql+3
    int node = quad * 4 + q;
    int beg = g_rowptr[node], end = g_rowptr[node + 1];
    int myc = end - beg;
    int m1 = __shfl_xor_sync(0xffffffffu, myc, 8);
    int mx = (myc > m1) ? myc : m1;
    int m2 = __shfl_xor_sync(0xffffffffu, mx, 16);
    int maxit = (mx > m2) ? mx : m2;
    const float2* __restrict__ in2 = (const float2*)g_A;   // 8B = 4 halves
    float4 acc = make_float4(0.f, 0.f, 0.f, 0.f);
    #pragma unroll 4
    for (int it = 0; it < maxit; it++) {
        int e = beg + it;
        if (e < end) {
            int2 cv = __ldg(&g_cv[e]);
            float nv = __int_as_float(cv.y);
            float2 packed = __ldg(&in2[cv.x * 8 + ql]);
            float2 h01 = __half22float2(*(const __half2*)&packed.x);
            float2 h23 = __half22float2(*(const __half2*)&packed.y);
            acc.x += nv * h01.x;
            acc.y += nv * h01.y;
            acc.z += nv * h23.x;
            acc.w += nv * h23.y;
        }
    }
    float dinv = __ldg(&g_deg[node]);
    float4 bv = __ldg(&((const float4*)bias)[ql]);
    acc.x = dinv * acc.x + bv.x;
    acc.y = dinv * acc.y + bv.y;
    acc.z = dinv * acc.z + bv.z;
    acc.w = dinv * acc.w + bv.w;
    if (relu) {
        acc.x = fmaxf(acc.x, 0.f);
        acc.y = fmaxf(acc.y, 0.f);
        acc.z = fmaxf(acc.z, 0.f);
        acc.w = fmaxf(acc.w, 0.f);
    }
    __half2 o0 = __floats2half2_rn(acc.x, acc.y);
    __half2 o1 = __floats2half2_rn(acc.z, acc.w);
    float2 ov;
    ov.x = *(float*)&o0;
    ov.y = *(float*)&o1;
    ((float2*)g_B)[node * 8 + ql] = ov;
}

// ---------------- mean pool (reads g_B fp16) --------------------------------
__global__ void k_pool(const int* __restrict__ batch) {
    int i = blockIdx.x * blockDim.x + threadIdx.x;
    if (i >= NN * 32) return;
    int n = i >> 5, f = i & 31;
    int b = batch[n];
    atomicAdd(&g_pool[b * 32 + f], __half2float(g_B[i]));
    if (f == 0) atomicAdd(&g_cnt[b], 1);
}

// ---------------- MLP head (single block) -----------------------------------
__global__ void k_mlp(const float* __restrict__ L1w, const float* __restrict__ L1b,
                      const float* __restrict__ L2w, const float* __restrict__ L2b,
                      const float* __restrict__ L3w, const float* __restrict__ L3b,
                      const float* __restrict__ L4w, const float* __restrict__ L4b,
                      float* __restrict__ out) {
    __shared__ float A[GG * MM];
    __shared__ float B[GG * MM];
    int tid = threadIdx.x;  // 256
    for (int i = tid; i < GG * HH; i += 256) {
        int g = i >> 5, f = i & 31;
        float c = (float)g_cnt[g];
        if (c < 1.f) c = 1.f;
        A[g * MM + f] = g_pool[i] / c;
    }
    __syncthreads();
    for (int i = tid; i < GG * MM; i += 256) {
        int g = i >> 6, m = i & 63;
        float a = L1b[m];
        #pragma unroll
        for (int k = 0; k < HH; k++) a += A[g * MM + k] * L1w[k * MM + m];
        B[g * MM + m] = fmaxf(a, 0.f);
    }
    __syncthreads();
    for (int i = tid; i < GG * MM; i += 256) {
        int g = i >> 6, m = i & 63;
        float a = L2b[m];
        #pragma unroll
        for (int k = 0; k < MM; k++) a += B[g * MM + k] * L2w[k * MM + m];
        A[g * MM + m] = fmaxf(a, 0.f);
    }
    __syncthreads();
    for (int i = tid; i < GG * MM; i += 256) {
        int g = i >> 6, m = i & 63;
        float a = L3b[m];
        #pragma unroll
        for (int k = 0; k < MM; k++) a += A[g * MM + k] * L3w[k * MM + m];
        B[g * MM + m] = fmaxf(a, 0.f);
    }
    __syncthreads();
    for (int i = tid; i < GG * CC; i += 256) {
        int g = i / CC, c = i - g * CC;
        float a = L4b[c];
        #pragma unroll
        for (int k = 0; k < MM; k++) a += B[g * MM + k] * L4w[k * CC + c];
        out[i] = a;
    }
}

// ---------------- launch -----------------------------------------------------
extern "C" void kernel_launch(void* const* d_in, const int* in_sizes, int n_in,
                              void* d_out, int out_size) {
    const float* x    = (const float*)d_in[0];
    const float* ew   = (const float*)d_in[1];
    const float* W1   = (const float*)d_in[2];
    const float* b1   = (const float*)d_in[3];
    const float* W2   = (const float*)d_in[4];
    const float* b2   = (const float*)d_in[5];
    const float* W3   = (const float*)d_in[6];
    const float* b3   = (const float*)d_in[7];
    const float* L1w  = (const float*)d_in[8];
    const float* L1b  = (const float*)d_in[9];
    const float* L2w  = (const float*)d_in[10];
    const float* L2b  = (const float*)d_in[11];
    const float* L3w  = (const float*)d_in[12];
    const float* L3b  = (const float*)d_in[13];
    const float* L4w  = (const float*)d_in[14];
    const float* L4b  = (const float*)d_in[15];
    const int*   ei   = (const int*)d_in[16];   // int32 (JAX x64 disabled)
    const int*   bat  = (const int*)d_in[17];   // int32
    float* out = (float*)d_out;

    const int nb_node  = (NN + 255) / 256;          // 391
    const int nb_edge  = (EA + 255) / 256;          // 12891
    const int nb_quad  = (NQUAD * 32 + 255) / 256;  // 3125
    const int nb_nwarp = (NN * 32 + 255) / 256;     // 12500

    k_zero<<<nb_node, 256>>>();
    k_hist<<<nb_edge, 256>>>(ei, ew);
    k_scanA<<<NB, 1024>>>();
    k_gemm128<<<nb_node, 256>>>(x, W1);   // needs only g_deg; placed here for ncu slot
    k_scanB<<<1, 128>>>();
    k_scanC<<<NB, 1024>>>();
    k_scatter<<<nb_edge, 256>>>(ei, ew);

    // conv1
    k_agg<<<nb_quad, 256>>>(b1, 1);
    // conv2
    k_gemm32<<<nb_node, 256>>>(W2);
    k_agg<<<nb_quad, 256>>>(b2, 1);
    // conv3
    k_gemm32<<<nb_node, 256>>>(W3);
    k_agg<<<nb_quad, 256>>>(b3, 0);

    k_pool<<<nb_nwarp, 256>>>(bat);
    k_mlp<<<1, 256>>>(L1w, L1b, L2w, L2b, L3w, L3b, L4w, L4b, out);
}